// round 11
// baseline (speedup 1.0000x reference)
#include <cuda_runtime.h>
#include <cuda_fp16.h>
#include <cstdint>

#define N_NODES 50000
#define N_EDGES 800000
#define D_IN    128
#define D_HID   256
#define D_OUT   128
#define NTILES  782
#define PGRID   152

// ---------------------------------------------------------------------------
// Device scratch
// ---------------------------------------------------------------------------
__device__ float  g_agg[(size_t)N_NODES * D_IN];
__device__ __half g_xh [(size_t)N_NODES * D_IN];
__device__ __half g_b1h[D_HID * D_IN];    // w1^T fp16 [256,128]
__device__ __half g_b2h[D_OUT * D_HID];   // w2^T fp16 [128,256]

// ---------------------------------------------------------------------------
// helpers
// ---------------------------------------------------------------------------
__device__ __forceinline__ uint32_t smem_u32(const void* p) {
    uint32_t a;
    asm("{ .reg .u64 t; cvta.to.shared.u64 t, %1; cvt.u32.u64 %0, t; }" : "=r"(a) : "l"(p));
    return a;
}
__device__ __forceinline__ uint32_t sw128(uint32_t off) { return off ^ ((off >> 3) & 0x70); }

__device__ __forceinline__ uint32_t pack2h(float a, float b) {
    __half2 h = __floats2half2_rn(a, b);
    return *reinterpret_cast<uint32_t*>(&h);
}
__device__ __forceinline__ void ldsm_x4(uint32_t* r, uint32_t addr) {
    asm volatile("ldmatrix.sync.aligned.m8n8.x4.shared.b16 {%0,%1,%2,%3}, [%4];"
                 : "=r"(r[0]), "=r"(r[1]), "=r"(r[2]), "=r"(r[3]) : "r"(addr));
}
__device__ __forceinline__ void mma_f16(float* c, const uint32_t* a, uint32_t b0, uint32_t b1) {
    asm volatile("mma.sync.aligned.m16n8k16.row.col.f32.f16.f16.f32 "
                 "{%0,%1,%2,%3}, {%4,%5,%6,%7}, {%8,%9}, {%0,%1,%2,%3};"
                 : "+f"(c[0]), "+f"(c[1]), "+f"(c[2]), "+f"(c[3])
                 : "r"(a[0]), "r"(a[1]), "r"(a[2]), "r"(a[3]), "r"(b0), "r"(b1));
}
__device__ __forceinline__ void sts16(uint32_t addr, uint4 v) {
    asm volatile("st.shared.v4.b32 [%0], {%1,%2,%3,%4};"
                 :: "r"(addr), "r"(v.x), "r"(v.y), "r"(v.z), "r"(v.w) : "memory");
}
__device__ __forceinline__ void sts4(uint32_t addr, uint32_t v) {
    asm volatile("st.shared.b32 [%0], %1;" :: "r"(addr), "r"(v) : "memory");
}
__device__ __forceinline__ void cp16(uint32_t dst, const void* src, uint32_t sz) {
    asm volatile("cp.async.cg.shared.global [%0], [%1], 16, %2;"
                 :: "r"(dst), "l"(src), "r"(sz) : "memory");
}
__device__ __forceinline__ void cp_commit() { asm volatile("cp.async.commit_group;" ::: "memory"); }
__device__ __forceinline__ void cp_wait0()  { asm volatile("cp.async.wait_group 0;" ::: "memory"); }

// ---------------------------------------------------------------------------
// init: agg = (1+eps)*x  AND  xh = fp16(x)
// ---------------------------------------------------------------------------
__global__ void init_kernel(const float* __restrict__ x,
                            const float* __restrict__ eps) {
    const float epsv = 1.0f + eps[0];
    size_t i = (size_t)blockIdx.x * blockDim.x + threadIdx.x;
    size_t n = (size_t)N_NODES * D_IN / 4;
    if (i < n) {
        float4 v = reinterpret_cast<const float4*>(x)[i];
        uint2 h;
        h.x = pack2h(v.x, v.y);
        h.y = pack2h(v.z, v.w);
        reinterpret_cast<uint2*>(g_xh)[i] = h;
        v.x *= epsv; v.y *= epsv; v.z *= epsv; v.w *= epsv;
        reinterpret_cast<float4*>(g_agg)[i] = v;
    }
}

// ---------------------------------------------------------------------------
// edge aggregation: unroll-4 batched gathers
// ---------------------------------------------------------------------------
#define EDGES_PER_WARP 128

__global__ __launch_bounds__(256) void agg_kernel(
    const int*   __restrict__ edge_src,
    const int*   __restrict__ edge_dst,
    const float* __restrict__ edge_val)
{
    int gtid   = blockIdx.x * blockDim.x + threadIdx.x;
    int warpId = gtid >> 5;
    int lane   = threadIdx.x & 31;

    long start = (long)warpId * EDGES_PER_WARP;
    if (start >= N_EDGES) return;
    long end = start + EDGES_PER_WARP;

    float ax = 0.f, ay = 0.f, az = 0.f, aw = 0.f;
    int cur_dst = edge_dst[start];

    for (long e = start; e < end; e += 4) {
        int4   d4 = *reinterpret_cast<const int4*>(edge_dst + e);
        int4   s4 = *reinterpret_cast<const int4*>(edge_src + e);
        float4 v4 = *reinterpret_cast<const float4*>(edge_val + e);
        uint2 h0 = *reinterpret_cast<const uint2*>(g_xh + (size_t)s4.x * D_IN + lane * 4);
        uint2 h1 = *reinterpret_cast<const uint2*>(g_xh + (size_t)s4.y * D_IN + lane * 4);
        uint2 h2 = *reinterpret_cast<const uint2*>(g_xh + (size_t)s4.z * D_IN + lane * 4);
        uint2 h3 = *reinterpret_cast<const uint2*>(g_xh + (size_t)s4.w * D_IN + lane * 4);

        #define PROC(dd, vv, hh)                                                   \
        do {                                                                       \
            if ((dd) != cur_dst) {                                                 \
                float* o = g_agg + (size_t)cur_dst * D_IN + lane * 4;              \
                atomicAdd(o + 0, ax); atomicAdd(o + 1, ay);                        \
                atomicAdd(o + 2, az); atomicAdd(o + 3, aw);                        \
                ax = ay = az = aw = 0.f;                                           \
                cur_dst = (dd);                                                    \
            }                                                                      \
            float2 p01 = __half22float2(*reinterpret_cast<__half2*>(&(hh).x));     \
            float2 p23 = __half22float2(*reinterpret_cast<__half2*>(&(hh).y));     \
            ax += (vv) * p01.x; ay += (vv) * p01.y;                                \
            az += (vv) * p23.x; aw += (vv) * p23.y;                                \
        } while (0)

        PROC(d4.x, v4.x, h0);
        PROC(d4.y, v4.y, h1);
        PROC(d4.z, v4.z, h2);
        PROC(d4.w, v4.w, h3);
        #undef PROC
    }
    float* o = g_agg + (size_t)cur_dst * D_IN + lane * 4;
    atomicAdd(o + 0, ax); atomicAdd(o + 1, ay);
    atomicAdd(o + 2, az); atomicAdd(o + 3, aw);
}

// ---------------------------------------------------------------------------
// weight transpose -> fp16
// ---------------------------------------------------------------------------
__global__ __launch_bounds__(256) void conv_b_kernel(const float* __restrict__ w1,
                                                     const float* __restrict__ w2)
{
    int idx = blockIdx.x * blockDim.x + threadIdx.x;
    if (idx < D_HID * D_IN) {
        int n = idx / D_IN, k = idx % D_IN;
        g_b1h[idx] = __float2half_rn(w1[(size_t)k * D_HID + n]);
    }
    int idx2 = idx - D_HID * D_IN;
    if (idx2 >= 0 && idx2 < D_OUT * D_HID) {
        int n = idx2 / D_HID, k = idx2 % D_HID;
        g_b2h[idx2] = __float2half_rn(w2[(size_t)k * D_OUT + n]);
    }
}

// ---------------------------------------------------------------------------
// FUSED MLP, persistent, 512 threads (16 warps, 4/SMSP). Per 64-row tile:
//   GEMM1 64x256 (warp grid 4x4, tile 16x64) -> bias+relu+split -> HID smem
//   GEMM2 64x128 (warp grid 4x4, tile 16x32) -> bias -> out fp32
// SMEM (224 KB): B1 0..64K | B2 64..128K | HID 128..192K | A 192..224K
// ---------------------------------------------------------------------------
__global__ __launch_bounds__(512, 1) void fused_kernel(
    const float* __restrict__ aggp,
    const __half* __restrict__ b1mat,
    const __half* __restrict__ b2mat,
    const float* __restrict__ bias1,
    const float* __restrict__ bias2,
    float* __restrict__ out)
{
    constexpr uint32_t B1_OF = 0, B2_OF = 65536, HID_OF = 131072, A_OF = 196608;

    extern __shared__ char smem[];
    const uint32_t sb = smem_u32(smem);

    const int tid  = threadIdx.x;
    const int lane = tid & 31;
    const int wid  = tid >> 5;
    const int wr   = wid >> 2;     // warp row 0..3 (16 rows each)
    const int wc   = wid & 3;      // warp col 0..3

    // ---- stage resident B1: [256,128] as 2 n-tiles x 2 k-subs x 16KB ----
    #pragma unroll
    for (int u = tid; u < 4096; u += 512) {
        int r = u >> 4, g = u & 15;
        int nt = r >> 7, rt = r & 127;
        int sub = g >> 3, gi = g & 7;
        cp16(sb + B1_OF + nt * 32768 + sub * 16384 + sw128((uint32_t)(rt * 128 + gi * 16)),
             b1mat + (size_t)r * D_IN + g * 8, 16u);
    }
    // ---- stage resident B2: [128,256] as 2 kc x 2 sub x 16KB ----
    #pragma unroll
    for (int u = tid; u < 4096; u += 512) {
        int r = u >> 5, g = u & 31;
        int kc = g >> 4, sub = (g >> 3) & 1, gi = g & 7;
        cp16(sb + B2_OF + kc * 32768 + sub * 16384 + sw128((uint32_t)(r * 128 + gi * 16)),
             b2mat + (size_t)r * D_HID + g * 8, 16u);
    }
    cp_commit();

    // ---- A prefetch into regs (16 floats/thread) ----
    float ar[16];
    auto lda = [&](int tile) {
        #pragma unroll
        for (int uu = 0; uu < 2; ++uu) {
            int u = tid + uu * 512;
            int r = u >> 4, g = u & 15;
            int row = tile * 64 + r;
            float* d = ar + uu * 8;
            if (row < N_NODES) {
                const float* pa = aggp + (size_t)row * D_IN + g * 8;
                float4 a0 = *reinterpret_cast<const float4*>(pa);
                float4 a1 = *reinterpret_cast<const float4*>(pa + 4);
                d[0] = a0.x; d[1] = a0.y; d[2] = a0.z; d[3] = a0.w;
                d[4] = a1.x; d[5] = a1.y; d[6] = a1.z; d[7] = a1.w;
            } else {
                #pragma unroll
                for (int j = 0; j < 8; ++j) d[j] = 0.f;
            }
        }
    };
    auto sta = [&]() {
        #pragma unroll
        for (int uu = 0; uu < 2; ++uu) {
            int u = tid + uu * 512;
            int r = u >> 4, g = u & 15;
            int sub = g >> 3, gi = g & 7;
            float* v = ar + uu * 8;
            float h[8], l[8];
            #pragma unroll
            for (int j = 0; j < 8; ++j) {
                h[j] = __half2float(__float2half_rn(v[j]));
                l[j] = v[j] - h[j];
            }
            uint32_t off = A_OF + sub * 8192 + sw128((uint32_t)(r * 128 + gi * 16));
            sts16(sb + off,
                  make_uint4(pack2h(h[0], h[1]), pack2h(h[2], h[3]),
                             pack2h(h[4], h[5]), pack2h(h[6], h[7])));
            sts16(sb + off + 16384,
                  make_uint4(pack2h(l[0], l[1]), pack2h(l[2], l[3]),
                             pack2h(l[4], l[5]), pack2h(l[6], l[7])));
        }
    };

    int t = blockIdx.x;
    lda(t);
    cp_wait0();
    sta();
    __syncthreads();

    while (t < NTILES) {
        const int tn = t + PGRID;
        const bool more = tn < NTILES;
        if (more) lda(tn);   // LDGs overlap GEMM1 MMAs

        const int row0 = t * 64;

        // ================= GEMM1: 64x256, warp tile 16x64 =================
        {
            const int wm0 = wr * 16;
            const int wn0 = wc * 64;
            float acc[8][4];
            #pragma unroll
            for (int j = 0; j < 8; ++j)
                #pragma unroll
                for (int q = 0; q < 4; ++q) acc[j][q] = 0.f;

            uint32_t ahf[2][4], alf[2][4], bhf[2][4][4];
            auto ld1 = [&](int ks, int slot) {
                const uint32_t ksubA = (uint32_t)(ks >> 2) * 8192;
                const uint32_t ksubB = (uint32_t)(ks >> 2) * 16384;
                const int kb = (ks & 3) * 32;
                {
                    uint32_t off = A_OF + ksubA +
                        sw128((uint32_t)((wm0 + (lane & 15)) * 128 +
                                         kb + (lane >> 4) * 16));
                    ldsm_x4(ahf[slot], sb + off);
                    ldsm_x4(alf[slot], sb + off + 16384);
                }
                #pragma unroll
                for (int pi = 0; pi < 4; ++pi) {
                    const int q = lane >> 3;
                    int nrow = wn0 + pi * 16 + ((q >> 1) << 3) + (lane & 7);
                    int ntt = nrow >> 7, rt = nrow & 127;
                    uint32_t off = B1_OF + ntt * 32768 + ksubB +
                        sw128((uint32_t)(rt * 128 + kb + (q & 1) * 16));
                    ldsm_x4(bhf[slot][pi], sb + off);
                }
            };
            ld1(0, 0);
            #pragma unroll
            for (int ks = 0; ks < 8; ++ks) {
                const int cur = ks & 1;
                if (ks < 7) ld1(ks + 1, cur ^ 1);
                #pragma unroll
                for (int pi = 0; pi < 4; ++pi)
                    #pragma unroll
                    for (int hh = 0; hh < 2; ++hh) {
                        float* c = acc[pi * 2 + hh];
                        mma_f16(c, ahf[cur], bhf[cur][pi][2 * hh], bhf[cur][pi][2 * hh + 1]);
                        mma_f16(c, alf[cur], bhf[cur][pi][2 * hh], bhf[cur][pi][2 * hh + 1]);
                    }
            }

            // epilogue: bias + relu + split -> HID smem
            #pragma unroll
            for (int ni = 0; ni < 8; ++ni) {
                int colb = wn0 + ni * 8 + (lane & 3) * 2;
                float2 bb = *reinterpret_cast<const float2*>(bias1 + colb);
                int kc = colb >> 7, sub = (colb >> 6) & 1, ci = (colb & 63) * 2;
                #pragma unroll
                for (int p = 0; p < 2; ++p) {
                    int r = wm0 + (lane >> 2) + p * 8;
                    float v0 = fmaxf(acc[ni][2 * p]     + bb.x, 0.f);
                    float v1 = fmaxf(acc[ni][2 * p + 1] + bb.y, 0.f);
                    float h0 = __half2float(__float2half_rn(v0));
                    float h1 = __half2float(__float2half_rn(v1));
                    uint32_t off = HID_OF + kc * 16384 + sub * 8192 +
                                   sw128((uint32_t)(r * 128 + ci));
                    sts4(sb + off,         pack2h(h0, h1));
                    sts4(sb + off + 32768, pack2h(v0 - h0, v1 - h1));
                }
            }
        }
        __syncthreads();   // HID visible; A reads done

        if (more) sta();   // STS next A; overlaps GEMM2 MMAs

        // ================= GEMM2: 64x128, warp tile 16x32 =================
        {
            const int wm0 = wr * 16;
            const int wn0 = wc * 32;
            float acc[4][4];
            #pragma unroll
            for (int j = 0; j < 4; ++j)
                #pragma unroll
                for (int q = 0; q < 4; ++q) acc[j][q] = 0.f;

            uint32_t ahf[2][4], alf[2][4], bhf[2][2][4];
            auto ld2 = [&](int ks, int slot) {
                const int kc = ks >> 3, k7 = ks & 7;
                const uint32_t ksubA = (uint32_t)kc * 16384 + (uint32_t)((ks >> 2) & 1) * 8192;
                const uint32_t ksubB = (uint32_t)kc * 32768 + (uint32_t)((ks >> 2) & 1) * 16384;
                const int kb = (k7 & 3) * 32;
                {
                    uint32_t off = HID_OF + ksubA +
                        sw128((uint32_t)((wm0 + (lane & 15)) * 128 +
                                         kb + (lane >> 4) * 16));
                    ldsm_x4(ahf[slot], sb + off);
                    ldsm_x4(alf[slot], sb + off + 32768);
                }
                #pragma unroll
                for (int pi = 0; pi < 2; ++pi) {
                    const int q = lane >> 3;
                    uint32_t off = B2_OF + ksubB + sw128((uint32_t)(
                        (wn0 + pi * 16 + ((q >> 1) << 3) + (lane & 7)) * 128 +
                        kb + (q & 1) * 16));
                    ldsm_x4(bhf[slot][pi], sb + off);
                }
            };
            ld2(0, 0);
            #pragma unroll
            for (int ks = 0; ks < 16; ++ks) {
                const int cur = ks & 1;
                if (ks < 15) ld2(ks + 1, cur ^ 1);
                #pragma unroll
                for (int pi = 0; pi < 2; ++pi)
                    #pragma unroll
                    for (int hh = 0; hh < 2; ++hh) {
                        float* c = acc[pi * 2 + hh];
                        mma_f16(c, ahf[cur], bhf[cur][pi][2 * hh], bhf[cur][pi][2 * hh + 1]);
                        mma_f16(c, alf[cur], bhf[cur][pi][2 * hh], bhf[cur][pi][2 * hh + 1]);
                    }
            }

            // epilogue -> out fp32
            #pragma unroll
            for (int ni = 0; ni < 4; ++ni) {
                int col = wn0 + ni * 8 + (lane & 3) * 2;
                int rbase = row0 + wm0 + (lane >> 2);
                float2 bb = *reinterpret_cast<const float2*>(bias2 + col);
                #pragma unroll
                for (int p = 0; p < 2; ++p) {
                    int row = rbase + p * 8;
                    if (row >= N_NODES) continue;
                    *reinterpret_cast<float2*>(out + (size_t)row * D_OUT + col) =
                        make_float2(acc[ni][2 * p] + bb.x,
                                    acc[ni][2 * p + 1] + bb.y);
                }
            }
        }
        __syncthreads();   // HID/A reuse safe next iteration
        t = tn;
    }
}

// ---------------------------------------------------------------------------
// Launch. Inputs: x, edge_src, edge_dst, edge_val, eps, w1, b1, w2, b2
// ---------------------------------------------------------------------------
extern "C" void kernel_launch(void* const* d_in, const int* in_sizes, int n_in,
                              void* d_out, int out_size)
{
    const float* x        = (const float*)d_in[0];
    const int*   edge_src = (const int*)  d_in[1];
    const int*   edge_dst = (const int*)  d_in[2];
    const float* edge_val = (const float*)d_in[3];
    const float* eps      = (const float*)d_in[4];
    const float* w1       = (const float*)d_in[5];
    const float* b1       = (const float*)d_in[6];
    const float* w2       = (const float*)d_in[7];
    const float* b2       = (const float*)d_in[8];
    float* out = (float*)d_out;

    float* aggp;
    __half *b1h, *b2h;
    cudaGetSymbolAddress((void**)&aggp, g_agg);
    cudaGetSymbolAddress((void**)&b1h,  g_b1h);
    cudaGetSymbolAddress((void**)&b2h,  g_b2h);

    {
        size_t n = (size_t)N_NODES * D_IN / 4;
        init_kernel<<<(int)((n + 255) / 256), 256>>>(x, eps);
    }
    {
        int warps = (N_EDGES + EDGES_PER_WARP - 1) / EDGES_PER_WARP;
        agg_kernel<<<(warps * 32 + 255) / 256, 256>>>(edge_src, edge_dst, edge_val);
    }
    conv_b_kernel<<<(D_HID * D_IN + D_OUT * D_HID + 255) / 256, 256>>>(w1, w2);

    {
        constexpr int SMEM = 229376;   // 224 KB
        cudaFuncSetAttribute(fused_kernel, cudaFuncAttributeMaxDynamicSharedMemorySize, SMEM);
        fused_kernel<<<PGRID, 512, SMEM>>>(aggp, b1h, b2h, b1, b2, out);
    }
}

// round 12
// speedup vs baseline: 1.1257x; 1.1257x over previous
#include <cuda_runtime.h>
#include <cuda_fp16.h>
#include <cstdint>

#define N_NODES 50000
#define N_EDGES 800000
#define D_IN    128
#define D_HID   256
#define D_OUT   128
#define NTILES  782
#define PGRID   152

// ---------------------------------------------------------------------------
// Device scratch
// ---------------------------------------------------------------------------
__device__ float  g_agg[(size_t)N_NODES * D_IN];
__device__ __half g_xh [(size_t)N_NODES * D_IN];
__device__ __half g_b1h[D_HID * D_IN];    // w1^T fp16 [256,128]
__device__ __half g_b2h[D_OUT * D_HID];   // w2^T fp16 [128,256]

// ---------------------------------------------------------------------------
// helpers
// ---------------------------------------------------------------------------
__device__ __forceinline__ uint32_t smem_u32(const void* p) {
    uint32_t a;
    asm("{ .reg .u64 t; cvta.to.shared.u64 t, %1; cvt.u32.u64 %0, t; }" : "=r"(a) : "l"(p));
    return a;
}
__device__ __forceinline__ uint32_t sw128(uint32_t off) { return off ^ ((off >> 3) & 0x70); }

__device__ __forceinline__ uint32_t pack2h(float a, float b) {
    __half2 h = __floats2half2_rn(a, b);
    return *reinterpret_cast<uint32_t*>(&h);
}
__device__ __forceinline__ void ldsm_x4(uint32_t* r, uint32_t addr) {
    asm volatile("ldmatrix.sync.aligned.m8n8.x4.shared.b16 {%0,%1,%2,%3}, [%4];"
                 : "=r"(r[0]), "=r"(r[1]), "=r"(r[2]), "=r"(r[3]) : "r"(addr));
}
__device__ __forceinline__ void mma_f16(float* c, const uint32_t* a, uint32_t b0, uint32_t b1) {
    asm volatile("mma.sync.aligned.m16n8k16.row.col.f32.f16.f16.f32 "
                 "{%0,%1,%2,%3}, {%4,%5,%6,%7}, {%8,%9}, {%0,%1,%2,%3};"
                 : "+f"(c[0]), "+f"(c[1]), "+f"(c[2]), "+f"(c[3])
                 : "r"(a[0]), "r"(a[1]), "r"(a[2]), "r"(a[3]), "r"(b0), "r"(b1));
}
__device__ __forceinline__ void sts16(uint32_t addr, uint4 v) {
    asm volatile("st.shared.v4.b32 [%0], {%1,%2,%3,%4};"
                 :: "r"(addr), "r"(v.x), "r"(v.y), "r"(v.z), "r"(v.w) : "memory");
}
__device__ __forceinline__ void sts4(uint32_t addr, uint32_t v) {
    asm volatile("st.shared.b32 [%0], %1;" :: "r"(addr), "r"(v) : "memory");
}
__device__ __forceinline__ void cp16(uint32_t dst, const void* src, uint32_t sz) {
    asm volatile("cp.async.cg.shared.global [%0], [%1], 16, %2;"
                 :: "r"(dst), "l"(src), "r"(sz) : "memory");
}
__device__ __forceinline__ void cp_commit() { asm volatile("cp.async.commit_group;" ::: "memory"); }
__device__ __forceinline__ void cp_wait0()  { asm volatile("cp.async.wait_group 0;" ::: "memory"); }

// ---------------------------------------------------------------------------
// init: agg = (1+eps)*x  AND  xh = fp16(x)
// ---------------------------------------------------------------------------
__global__ void init_kernel(const float* __restrict__ x,
                            const float* __restrict__ eps) {
    const float epsv = 1.0f + eps[0];
    size_t i = (size_t)blockIdx.x * blockDim.x + threadIdx.x;
    size_t n = (size_t)N_NODES * D_IN / 4;
    if (i < n) {
        float4 v = reinterpret_cast<const float4*>(x)[i];
        uint2 h;
        h.x = pack2h(v.x, v.y);
        h.y = pack2h(v.z, v.w);
        reinterpret_cast<uint2*>(g_xh)[i] = h;
        v.x *= epsv; v.y *= epsv; v.z *= epsv; v.w *= epsv;
        reinterpret_cast<float4*>(g_agg)[i] = v;
    }
}

// ---------------------------------------------------------------------------
// edge aggregation: unroll-4 batched gathers
// ---------------------------------------------------------------------------
#define EDGES_PER_WARP 128

__global__ __launch_bounds__(256) void agg_kernel(
    const int*   __restrict__ edge_src,
    const int*   __restrict__ edge_dst,
    const float* __restrict__ edge_val)
{
    int gtid   = blockIdx.x * blockDim.x + threadIdx.x;
    int warpId = gtid >> 5;
    int lane   = threadIdx.x & 31;

    long start = (long)warpId * EDGES_PER_WARP;
    if (start >= N_EDGES) return;
    long end = start + EDGES_PER_WARP;

    float ax = 0.f, ay = 0.f, az = 0.f, aw = 0.f;
    int cur_dst = edge_dst[start];

    for (long e = start; e < end; e += 4) {
        int4   d4 = *reinterpret_cast<const int4*>(edge_dst + e);
        int4   s4 = *reinterpret_cast<const int4*>(edge_src + e);
        float4 v4 = *reinterpret_cast<const float4*>(edge_val + e);
        uint2 h0 = *reinterpret_cast<const uint2*>(g_xh + (size_t)s4.x * D_IN + lane * 4);
        uint2 h1 = *reinterpret_cast<const uint2*>(g_xh + (size_t)s4.y * D_IN + lane * 4);
        uint2 h2 = *reinterpret_cast<const uint2*>(g_xh + (size_t)s4.z * D_IN + lane * 4);
        uint2 h3 = *reinterpret_cast<const uint2*>(g_xh + (size_t)s4.w * D_IN + lane * 4);

        #define PROC(dd, vv, hh)                                                   \
        do {                                                                       \
            if ((dd) != cur_dst) {                                                 \
                float* o = g_agg + (size_t)cur_dst * D_IN + lane * 4;              \
                atomicAdd(o + 0, ax); atomicAdd(o + 1, ay);                        \
                atomicAdd(o + 2, az); atomicAdd(o + 3, aw);                        \
                ax = ay = az = aw = 0.f;                                           \
                cur_dst = (dd);                                                    \
            }                                                                      \
            float2 p01 = __half22float2(*reinterpret_cast<__half2*>(&(hh).x));     \
            float2 p23 = __half22float2(*reinterpret_cast<__half2*>(&(hh).y));     \
            ax += (vv) * p01.x; ay += (vv) * p01.y;                                \
            az += (vv) * p23.x; aw += (vv) * p23.y;                                \
        } while (0)

        PROC(d4.x, v4.x, h0);
        PROC(d4.y, v4.y, h1);
        PROC(d4.z, v4.z, h2);
        PROC(d4.w, v4.w, h3);
        #undef PROC
    }
    float* o = g_agg + (size_t)cur_dst * D_IN + lane * 4;
    atomicAdd(o + 0, ax); atomicAdd(o + 1, ay);
    atomicAdd(o + 2, az); atomicAdd(o + 3, aw);
}

// ---------------------------------------------------------------------------
// weight transpose -> fp16
// ---------------------------------------------------------------------------
__global__ __launch_bounds__(256) void conv_b_kernel(const float* __restrict__ w1,
                                                     const float* __restrict__ w2)
{
    int idx = blockIdx.x * blockDim.x + threadIdx.x;
    if (idx < D_HID * D_IN) {
        int n = idx / D_IN, k = idx % D_IN;
        g_b1h[idx] = __float2half_rn(w1[(size_t)k * D_HID + n]);
    }
    int idx2 = idx - D_HID * D_IN;
    if (idx2 >= 0 && idx2 < D_OUT * D_HID) {
        int n = idx2 / D_HID, k = idx2 % D_HID;
        g_b2h[idx2] = __float2half_rn(w2[(size_t)k * D_OUT + n]);
    }
}

// ---------------------------------------------------------------------------
// FUSED MLP, persistent, 512 threads (16 warps). NO lo-split (pure fp16 A/B).
// Per 64-row tile:
//   GEMM1 64x256 (4x4 warps, tile 16x64) -> bias+relu -> HID fp16 smem
//   GEMM2 64x128 (4x4 warps, tile 16x32) -> bias -> out fp32
// SMEM: B1 0..64K | B2 64..128K | HID 128..160K | A 160..176K  (176 KB)
// ---------------------------------------------------------------------------
__global__ __launch_bounds__(512, 1) void fused_kernel(
    const float* __restrict__ aggp,
    const __half* __restrict__ b1mat,
    const __half* __restrict__ b2mat,
    const float* __restrict__ bias1,
    const float* __restrict__ bias2,
    float* __restrict__ out)
{
    constexpr uint32_t B1_OF = 0, B2_OF = 65536, HID_OF = 131072, A_OF = 163840;

    extern __shared__ char smem[];
    const uint32_t sb = smem_u32(smem);

    const int tid  = threadIdx.x;
    const int lane = tid & 31;
    const int wid  = tid >> 5;
    const int wr   = wid >> 2;
    const int wc   = wid & 3;

    // ---- stage resident B1 ----
    #pragma unroll
    for (int u = tid; u < 4096; u += 512) {
        int r = u >> 4, g = u & 15;
        int nt = r >> 7, rt = r & 127;
        int sub = g >> 3, gi = g & 7;
        cp16(sb + B1_OF + nt * 32768 + sub * 16384 + sw128((uint32_t)(rt * 128 + gi * 16)),
             b1mat + (size_t)r * D_IN + g * 8, 16u);
    }
    // ---- stage resident B2 ----
    #pragma unroll
    for (int u = tid; u < 4096; u += 512) {
        int r = u >> 5, g = u & 31;
        int kc = g >> 4, sub = (g >> 3) & 1, gi = g & 7;
        cp16(sb + B2_OF + kc * 32768 + sub * 16384 + sw128((uint32_t)(r * 128 + gi * 16)),
             b2mat + (size_t)r * D_HID + g * 8, 16u);
    }
    cp_commit();

    // ---- A prefetch into regs (16 floats/thread) ----
    float ar[16];
    auto lda = [&](int tile) {
        #pragma unroll
        for (int uu = 0; uu < 2; ++uu) {
            int u = tid + uu * 512;
            int r = u >> 4, g = u & 15;
            int row = tile * 64 + r;
            float* d = ar + uu * 8;
            if (row < N_NODES) {
                const float* pa = aggp + (size_t)row * D_IN + g * 8;
                float4 a0 = *reinterpret_cast<const float4*>(pa);
                float4 a1 = *reinterpret_cast<const float4*>(pa + 4);
                d[0] = a0.x; d[1] = a0.y; d[2] = a0.z; d[3] = a0.w;
                d[4] = a1.x; d[5] = a1.y; d[6] = a1.z; d[7] = a1.w;
            } else {
                #pragma unroll
                for (int j = 0; j < 8; ++j) d[j] = 0.f;
            }
        }
    };
    auto sta = [&]() {   // convert ar -> fp16 -> A_OF (hi only)
        #pragma unroll
        for (int uu = 0; uu < 2; ++uu) {
            int u = tid + uu * 512;
            int r = u >> 4, g = u & 15;
            int sub = g >> 3, gi = g & 7;
            float* v = ar + uu * 8;
            uint32_t off = A_OF + sub * 8192 + sw128((uint32_t)(r * 128 + gi * 16));
            sts16(sb + off,
                  make_uint4(pack2h(v[0], v[1]), pack2h(v[2], v[3]),
                             pack2h(v[4], v[5]), pack2h(v[6], v[7])));
        }
    };

    int t = blockIdx.x;
    lda(t);
    cp_wait0();
    sta();
    __syncthreads();

    while (t < NTILES) {
        const int tn = t + PGRID;
        const bool more = tn < NTILES;
        if (more) lda(tn);   // LDGs overlap GEMM1 MMAs

        const int row0 = t * 64;

        // ================= GEMM1: 64x256, warp tile 16x64 =================
        {
            const int wm0 = wr * 16;
            const int wn0 = wc * 64;
            float acc[8][4];
            #pragma unroll
            for (int j = 0; j < 8; ++j)
                #pragma unroll
                for (int q = 0; q < 4; ++q) acc[j][q] = 0.f;

            uint32_t ahf[2][4], bhf[2][4][4];
            auto ld1 = [&](int ks, int slot) {
                const uint32_t ksubA = (uint32_t)(ks >> 2) * 8192;
                const uint32_t ksubB = (uint32_t)(ks >> 2) * 16384;
                const int kb = (ks & 3) * 32;
                {
                    uint32_t off = A_OF + ksubA +
                        sw128((uint32_t)((wm0 + (lane & 15)) * 128 +
                                         kb + (lane >> 4) * 16));
                    ldsm_x4(ahf[slot], sb + off);
                }
                #pragma unroll
                for (int pi = 0; pi < 4; ++pi) {
                    const int q = lane >> 3;
                    int nrow = wn0 + pi * 16 + ((q >> 1) << 3) + (lane & 7);
                    int ntt = nrow >> 7, rt = nrow & 127;
                    uint32_t off = B1_OF + ntt * 32768 + ksubB +
                        sw128((uint32_t)(rt * 128 + kb + (q & 1) * 16));
                    ldsm_x4(bhf[slot][pi], sb + off);
                }
            };
            ld1(0, 0);
            #pragma unroll
            for (int ks = 0; ks < 8; ++ks) {
                const int cur = ks & 1;
                if (ks < 7) ld1(ks + 1, cur ^ 1);
                #pragma unroll
                for (int pi = 0; pi < 4; ++pi)
                    #pragma unroll
                    for (int hh = 0; hh < 2; ++hh)
                        mma_f16(acc[pi * 2 + hh], ahf[cur],
                                bhf[cur][pi][2 * hh], bhf[cur][pi][2 * hh + 1]);
            }

            // epilogue: bias + relu -> HID fp16 smem
            #pragma unroll
            for (int ni = 0; ni < 8; ++ni) {
                int colb = wn0 + ni * 8 + (lane & 3) * 2;
                float2 bb = *reinterpret_cast<const float2*>(bias1 + colb);
                int kc = colb >> 7, sub = (colb >> 6) & 1, ci = (colb & 63) * 2;
                #pragma unroll
                for (int p = 0; p < 2; ++p) {
                    int r = wm0 + (lane >> 2) + p * 8;
                    float v0 = fmaxf(acc[ni][2 * p]     + bb.x, 0.f);
                    float v1 = fmaxf(acc[ni][2 * p + 1] + bb.y, 0.f);
                    uint32_t off = HID_OF + kc * 16384 + sub * 8192 +
                                   sw128((uint32_t)(r * 128 + ci));
                    sts4(sb + off, pack2h(v0, v1));
                }
            }
        }
        __syncthreads();   // HID visible; A reads done

        if (more) sta();   // STS next A; overlaps GEMM2 MMAs

        // ================= GEMM2: 64x128, warp tile 16x32 =================
        {
            const int wm0 = wr * 16;
            const int wn0 = wc * 32;
            float acc[4][4];
            #pragma unroll
            for (int j = 0; j < 4; ++j)
                #pragma unroll
                for (int q = 0; q < 4; ++q) acc[j][q] = 0.f;

            uint32_t ahf[2][4], bhf[2][2][4];
            auto ld2 = [&](int ks, int slot) {
                const int kc = ks >> 3, k7 = ks & 7;
                const uint32_t ksubA = (uint32_t)kc * 16384 + (uint32_t)((ks >> 2) & 1) * 8192;
                const uint32_t ksubB = (uint32_t)kc * 32768 + (uint32_t)((ks >> 2) & 1) * 16384;
                const int kb = (k7 & 3) * 32;
                {
                    uint32_t off = HID_OF + ksubA +
                        sw128((uint32_t)((wm0 + (lane & 15)) * 128 +
                                         kb + (lane >> 4) * 16));
                    ldsm_x4(ahf[slot], sb + off);
                }
                #pragma unroll
                for (int pi = 0; pi < 2; ++pi) {
                    const int q = lane >> 3;
                    uint32_t off = B2_OF + ksubB + sw128((uint32_t)(
                        (wn0 + pi * 16 + ((q >> 1) << 3) + (lane & 7)) * 128 +
                        kb + (q & 1) * 16));
                    ldsm_x4(bhf[slot][pi], sb + off);
                }
            };
            ld2(0, 0);
            #pragma unroll
            for (int ks = 0; ks < 16; ++ks) {
                const int cur = ks & 1;
                if (ks < 15) ld2(ks + 1, cur ^ 1);
                #pragma unroll
                for (int pi = 0; pi < 2; ++pi)
                    #pragma unroll
                    for (int hh = 0; hh < 2; ++hh)
                        mma_f16(acc[pi * 2 + hh], ahf[cur],
                                bhf[cur][pi][2 * hh], bhf[cur][pi][2 * hh + 1]);
            }

            // epilogue -> out fp32
            #pragma unroll
            for (int ni = 0; ni < 4; ++ni) {
                int col = wn0 + ni * 8 + (lane & 3) * 2;
                int rbase = row0 + wm0 + (lane >> 2);
                float2 bb = *reinterpret_cast<const float2*>(bias2 + col);
                #pragma unroll
                for (int p = 0; p < 2; ++p) {
                    int row = rbase + p * 8;
                    if (row >= N_NODES) continue;
                    *reinterpret_cast<float2*>(out + (size_t)row * D_OUT + col) =
                        make_float2(acc[ni][2 * p] + bb.x,
                                    acc[ni][2 * p + 1] + bb.y);
                }
            }
        }
        __syncthreads();
        t = tn;
    }
}

// ---------------------------------------------------------------------------
// Launch. Inputs: x, edge_src, edge_dst, edge_val, eps, w1, b1, w2, b2
// ---------------------------------------------------------------------------
extern "C" void kernel_launch(void* const* d_in, const int* in_sizes, int n_in,
                              void* d_out, int out_size)
{
    const float* x        = (const float*)d_in[0];
    const int*   edge_src = (const int*)  d_in[1];
    const int*   edge_dst = (const int*)  d_in[2];
    const float* edge_val = (const float*)d_in[3];
    const float* eps      = (const float*)d_in[4];
    const float* w1       = (const float*)d_in[5];
    const float* b1       = (const float*)d_in[6];
    const float* w2       = (const float*)d_in[7];
    const float* b2       = (const float*)d_in[8];
    float* out = (float*)d_out;

    float* aggp;
    __half *b1h, *b2h;
    cudaGetSymbolAddress((void**)&aggp, g_agg);
    cudaGetSymbolAddress((void**)&b1h,  g_b1h);
    cudaGetSymbolAddress((void**)&b2h,  g_b2h);

    {
        size_t n = (size_t)N_NODES * D_IN / 4;
        init_kernel<<<(int)((n + 255) / 256), 256>>>(x, eps);
    }
    {
        int warps = (N_EDGES + EDGES_PER_WARP - 1) / EDGES_PER_WARP;
        agg_kernel<<<(warps * 32 + 255) / 256, 256>>>(edge_src, edge_dst, edge_val);
    }
    conv_b_kernel<<<(D_HID * D_IN + D_OUT * D_HID + 255) / 256, 256>>>(w1, w2);

    {
        constexpr int SMEM = 180224;   // 176 KB
        cudaFuncSetAttribute(fused_kernel, cudaFuncAttributeMaxDynamicSharedMemorySize, SMEM);
        fused_kernel<<<PGRID, 512, SMEM>>>(aggp, b1h, b2h, b1, b2, out);
    }
}

// round 13
// speedup vs baseline: 1.1970x; 1.0634x over previous
#include <cuda_runtime.h>
#include <cuda_fp16.h>
#include <cstdint>

#define N_NODES 50000
#define N_EDGES 800000
#define D_IN    128
#define D_HID   256
#define D_OUT   128
#define NTILES  782
#define PGRID   152

// ---------------------------------------------------------------------------
// Device scratch
// ---------------------------------------------------------------------------
__device__ float  g_agg[(size_t)N_NODES * D_IN];
__device__ __half g_xh [(size_t)N_NODES * D_IN];
__device__ __half g_b1h[D_HID * D_IN];    // w1^T fp16 [256,128]
__device__ __half g_b2h[D_OUT * D_HID];   // w2^T fp16 [128,256]

// ---------------------------------------------------------------------------
// helpers
// ---------------------------------------------------------------------------
__device__ __forceinline__ uint32_t smem_u32(const void* p) {
    uint32_t a;
    asm("{ .reg .u64 t; cvta.to.shared.u64 t, %1; cvt.u32.u64 %0, t; }" : "=r"(a) : "l"(p));
    return a;
}
__device__ __forceinline__ uint32_t sw128(uint32_t off) { return off ^ ((off >> 3) & 0x70); }

__device__ __forceinline__ uint32_t pack2h(float a, float b) {
    __half2 h = __floats2half2_rn(a, b);
    return *reinterpret_cast<uint32_t*>(&h);
}
__device__ __forceinline__ void ldsm_x4(uint32_t* r, uint32_t addr) {
    asm volatile("ldmatrix.sync.aligned.m8n8.x4.shared.b16 {%0,%1,%2,%3}, [%4];"
                 : "=r"(r[0]), "=r"(r[1]), "=r"(r[2]), "=r"(r[3]) : "r"(addr));
}
__device__ __forceinline__ void mma_f16(float* c, const uint32_t* a, uint32_t b0, uint32_t b1) {
    asm volatile("mma.sync.aligned.m16n8k16.row.col.f32.f16.f16.f32 "
                 "{%0,%1,%2,%3}, {%4,%5,%6,%7}, {%8,%9}, {%0,%1,%2,%3};"
                 : "+f"(c[0]), "+f"(c[1]), "+f"(c[2]), "+f"(c[3])
                 : "r"(a[0]), "r"(a[1]), "r"(a[2]), "r"(a[3]), "r"(b0), "r"(b1));
}
__device__ __forceinline__ void sts16(uint32_t addr, uint4 v) {
    asm volatile("st.shared.v4.b32 [%0], {%1,%2,%3,%4};"
                 :: "r"(addr), "r"(v.x), "r"(v.y), "r"(v.z), "r"(v.w) : "memory");
}
__device__ __forceinline__ void sts4(uint32_t addr, uint32_t v) {
    asm volatile("st.shared.b32 [%0], %1;" :: "r"(addr), "r"(v) : "memory");
}
__device__ __forceinline__ void cp16(uint32_t dst, const void* src, uint32_t sz) {
    asm volatile("cp.async.cg.shared.global [%0], [%1], 16, %2;"
                 :: "r"(dst), "l"(src), "r"(sz) : "memory");
}
__device__ __forceinline__ void cp_commit() { asm volatile("cp.async.commit_group;" ::: "memory"); }
__device__ __forceinline__ void cp_wait0()  { asm volatile("cp.async.wait_group 0;" ::: "memory"); }

// ---------------------------------------------------------------------------
// init: agg = (1+eps)*x  AND  xh = fp16(x)
// ---------------------------------------------------------------------------
__global__ void init_kernel(const float* __restrict__ x,
                            const float* __restrict__ eps) {
    const float epsv = 1.0f + eps[0];
    size_t i = (size_t)blockIdx.x * blockDim.x + threadIdx.x;
    size_t n = (size_t)N_NODES * D_IN / 4;
    if (i < n) {
        float4 v = reinterpret_cast<const float4*>(x)[i];
        uint2 h;
        h.x = pack2h(v.x, v.y);
        h.y = pack2h(v.z, v.w);
        reinterpret_cast<uint2*>(g_xh)[i] = h;
        v.x *= epsv; v.y *= epsv; v.z *= epsv; v.w *= epsv;
        reinterpret_cast<float4*>(g_agg)[i] = v;
    }
}

// ---------------------------------------------------------------------------
// edge aggregation: unroll-4 batched gathers
// ---------------------------------------------------------------------------
#define EDGES_PER_WARP 128

__global__ __launch_bounds__(256) void agg_kernel(
    const int*   __restrict__ edge_src,
    const int*   __restrict__ edge_dst,
    const float* __restrict__ edge_val)
{
    int gtid   = blockIdx.x * blockDim.x + threadIdx.x;
    int warpId = gtid >> 5;
    int lane   = threadIdx.x & 31;

    long start = (long)warpId * EDGES_PER_WARP;
    if (start >= N_EDGES) return;
    long end = start + EDGES_PER_WARP;

    float ax = 0.f, ay = 0.f, az = 0.f, aw = 0.f;
    int cur_dst = edge_dst[start];

    for (long e = start; e < end; e += 4) {
        int4   d4 = *reinterpret_cast<const int4*>(edge_dst + e);
        int4   s4 = *reinterpret_cast<const int4*>(edge_src + e);
        float4 v4 = *reinterpret_cast<const float4*>(edge_val + e);
        uint2 h0 = *reinterpret_cast<const uint2*>(g_xh + (size_t)s4.x * D_IN + lane * 4);
        uint2 h1 = *reinterpret_cast<const uint2*>(g_xh + (size_t)s4.y * D_IN + lane * 4);
        uint2 h2 = *reinterpret_cast<const uint2*>(g_xh + (size_t)s4.z * D_IN + lane * 4);
        uint2 h3 = *reinterpret_cast<const uint2*>(g_xh + (size_t)s4.w * D_IN + lane * 4);

        #define PROC(dd, vv, hh)                                                   \
        do {                                                                       \
            if ((dd) != cur_dst) {                                                 \
                float* o = g_agg + (size_t)cur_dst * D_IN + lane * 4;              \
                atomicAdd(o + 0, ax); atomicAdd(o + 1, ay);                        \
                atomicAdd(o + 2, az); atomicAdd(o + 3, aw);                        \
                ax = ay = az = aw = 0.f;                                           \
                cur_dst = (dd);                                                    \
            }                                                                      \
            float2 p01 = __half22float2(*reinterpret_cast<__half2*>(&(hh).x));     \
            float2 p23 = __half22float2(*reinterpret_cast<__half2*>(&(hh).y));     \
            ax += (vv) * p01.x; ay += (vv) * p01.y;                                \
            az += (vv) * p23.x; aw += (vv) * p23.y;                                \
        } while (0)

        PROC(d4.x, v4.x, h0);
        PROC(d4.y, v4.y, h1);
        PROC(d4.z, v4.z, h2);
        PROC(d4.w, v4.w, h3);
        #undef PROC
    }
    float* o = g_agg + (size_t)cur_dst * D_IN + lane * 4;
    atomicAdd(o + 0, ax); atomicAdd(o + 1, ay);
    atomicAdd(o + 2, az); atomicAdd(o + 3, aw);
}

// ---------------------------------------------------------------------------
// weight transpose -> fp16
// ---------------------------------------------------------------------------
__global__ __launch_bounds__(256) void conv_b_kernel(const float* __restrict__ w1,
                                                     const float* __restrict__ w2)
{
    int idx = blockIdx.x * blockDim.x + threadIdx.x;
    if (idx < D_HID * D_IN) {
        int n = idx / D_IN, k = idx % D_IN;
        g_b1h[idx] = __float2half_rn(w1[(size_t)k * D_HID + n]);
    }
    int idx2 = idx - D_HID * D_IN;
    if (idx2 >= 0 && idx2 < D_OUT * D_HID) {
        int n = idx2 / D_HID, k = idx2 % D_HID;
        g_b2h[idx2] = __float2half_rn(w2[(size_t)k * D_OUT + n]);
    }
}

// ---------------------------------------------------------------------------
// FUSED MLP, persistent, 256 threads (8 warps, 2 row x 4 col). fp16 1-term.
// Per 64-row tile:
//   GEMM1 64x256, warp tile 32x64 -> bias+relu -> HID fp16 smem
//   GEMM2 64x128, warp tile 32x32 -> bias -> out fp32
// SMEM: B1 0..64K | B2 64..128K | HID 128..160K | A 160..176K  (176 KB)
// ---------------------------------------------------------------------------
__global__ __launch_bounds__(256, 1) void fused_kernel(
    const float* __restrict__ aggp,
    const __half* __restrict__ b1mat,
    const __half* __restrict__ b2mat,
    const float* __restrict__ bias1,
    const float* __restrict__ bias2,
    float* __restrict__ out)
{
    constexpr uint32_t B1_OF = 0, B2_OF = 65536, HID_OF = 131072, A_OF = 163840;

    extern __shared__ char smem[];
    const uint32_t sb = smem_u32(smem);

    const int tid  = threadIdx.x;
    const int lane = tid & 31;
    const int wid  = tid >> 5;
    const int wr   = wid >> 2;     // 0..1 (32 rows each)
    const int wc   = wid & 3;      // 0..3

    // ---- stage resident B1 ----
    #pragma unroll
    for (int u = tid; u < 4096; u += 256) {
        int r = u >> 4, g = u & 15;
        int nt = r >> 7, rt = r & 127;
        int sub = g >> 3, gi = g & 7;
        cp16(sb + B1_OF + nt * 32768 + sub * 16384 + sw128((uint32_t)(rt * 128 + gi * 16)),
             b1mat + (size_t)r * D_IN + g * 8, 16u);
    }
    // ---- stage resident B2 ----
    #pragma unroll
    for (int u = tid; u < 4096; u += 256) {
        int r = u >> 5, g = u & 31;
        int kc = g >> 4, sub = (g >> 3) & 1, gi = g & 7;
        cp16(sb + B2_OF + kc * 32768 + sub * 16384 + sw128((uint32_t)(r * 128 + gi * 16)),
             b2mat + (size_t)r * D_HID + g * 8, 16u);
    }
    cp_commit();

    // ---- A prefetch into regs (32 floats/thread) ----
    float ar[32];
    auto lda = [&](int tile) {
        #pragma unroll
        for (int uu = 0; uu < 4; ++uu) {
            int u = tid + uu * 256;
            int r = u >> 4, g = u & 15;
            int row = tile * 64 + r;
            float* d = ar + uu * 8;
            if (row < N_NODES) {
                const float* pa = aggp + (size_t)row * D_IN + g * 8;
                float4 a0 = *reinterpret_cast<const float4*>(pa);
                float4 a1 = *reinterpret_cast<const float4*>(pa + 4);
                d[0] = a0.x; d[1] = a0.y; d[2] = a0.z; d[3] = a0.w;
                d[4] = a1.x; d[5] = a1.y; d[6] = a1.z; d[7] = a1.w;
            } else {
                #pragma unroll
                for (int j = 0; j < 8; ++j) d[j] = 0.f;
            }
        }
    };
    auto sta = [&]() {   // ar -> fp16 -> A_OF
        #pragma unroll
        for (int uu = 0; uu < 4; ++uu) {
            int u = tid + uu * 256;
            int r = u >> 4, g = u & 15;
            int sub = g >> 3, gi = g & 7;
            float* v = ar + uu * 8;
            uint32_t off = A_OF + sub * 8192 + sw128((uint32_t)(r * 128 + gi * 16));
            sts16(sb + off,
                  make_uint4(pack2h(v[0], v[1]), pack2h(v[2], v[3]),
                             pack2h(v[4], v[5]), pack2h(v[6], v[7])));
        }
    };

    int t = blockIdx.x;
    lda(t);
    cp_wait0();
    sta();
    __syncthreads();

    while (t < NTILES) {
        const int tn = t + PGRID;
        const bool more = tn < NTILES;
        if (more) lda(tn);   // LDGs overlap GEMM1 MMAs

        const int row0 = t * 64;

        // ================= GEMM1: 64x256, warp tile 32x64 =================
        {
            const int wm0 = wr * 32;
            const int wn0 = wc * 64;
            float acc[2][8][4];
            #pragma unroll
            for (int i = 0; i < 2; ++i)
                #pragma unroll
                for (int j = 0; j < 8; ++j)
                    #pragma unroll
                    for (int q = 0; q < 4; ++q) acc[i][j][q] = 0.f;

            uint32_t ahf[2][2][4], bhf[2][4][4];
            auto ld1 = [&](int ks, int slot) {
                const uint32_t ksubA = (uint32_t)(ks >> 2) * 8192;
                const uint32_t ksubB = (uint32_t)(ks >> 2) * 16384;
                const int kb = (ks & 3) * 32;
                #pragma unroll
                for (int mi = 0; mi < 2; ++mi) {
                    uint32_t off = A_OF + ksubA +
                        sw128((uint32_t)((wm0 + mi * 16 + (lane & 15)) * 128 +
                                         kb + (lane >> 4) * 16));
                    ldsm_x4(ahf[slot][mi], sb + off);
                }
                #pragma unroll
                for (int pi = 0; pi < 4; ++pi) {
                    const int q = lane >> 3;
                    int nrow = wn0 + pi * 16 + ((q >> 1) << 3) + (lane & 7);
                    int ntt = nrow >> 7, rt = nrow & 127;
                    uint32_t off = B1_OF + ntt * 32768 + ksubB +
                        sw128((uint32_t)(rt * 128 + kb + (q & 1) * 16));
                    ldsm_x4(bhf[slot][pi], sb + off);
                }
            };
            ld1(0, 0);
            #pragma unroll
            for (int ks = 0; ks < 8; ++ks) {
                const int cur = ks & 1;
                if (ks < 7) ld1(ks + 1, cur ^ 1);
                #pragma unroll
                for (int mi = 0; mi < 2; ++mi)
                    #pragma unroll
                    for (int pi = 0; pi < 4; ++pi)
                        #pragma unroll
                        for (int hh = 0; hh < 2; ++hh)
                            mma_f16(acc[mi][pi * 2 + hh], ahf[cur][mi],
                                    bhf[cur][pi][2 * hh], bhf[cur][pi][2 * hh + 1]);
            }

            // epilogue: bias + relu -> HID fp16 smem
            #pragma unroll
            for (int mi = 0; mi < 2; ++mi) {
                #pragma unroll
                for (int ni = 0; ni < 8; ++ni) {
                    int colb = wn0 + ni * 8 + (lane & 3) * 2;
                    float2 bb = *reinterpret_cast<const float2*>(bias1 + colb);
                    int kc = colb >> 7, sub = (colb >> 6) & 1, ci = (colb & 63) * 2;
                    #pragma unroll
                    for (int p = 0; p < 2; ++p) {
                        int r = wm0 + mi * 16 + (lane >> 2) + p * 8;
                        float v0 = fmaxf(acc[mi][ni][2 * p]     + bb.x, 0.f);
                        float v1 = fmaxf(acc[mi][ni][2 * p + 1] + bb.y, 0.f);
                        uint32_t off = HID_OF + kc * 16384 + sub * 8192 +
                                       sw128((uint32_t)(r * 128 + ci));
                        sts4(sb + off, pack2h(v0, v1));
                    }
                }
            }
        }
        __syncthreads();   // HID visible; A reads done

        if (more) sta();   // STS next A; overlaps GEMM2 MMAs

        // ================= GEMM2: 64x128, warp tile 32x32 =================
        {
            const int wm0 = wr * 32;
            const int wn0 = wc * 32;
            float acc[2][4][4];
            #pragma unroll
            for (int i = 0; i < 2; ++i)
                #pragma unroll
                for (int j = 0; j < 4; ++j)
                    #pragma unroll
                    for (int q = 0; q < 4; ++q) acc[i][j][q] = 0.f;

            uint32_t ahf[2][2][4], bhf[2][2][4];
            auto ld2 = [&](int ks, int slot) {
                const int kc = ks >> 3, k7 = ks & 7;
                const uint32_t ksubA = (uint32_t)kc * 16384 + (uint32_t)((ks >> 2) & 1) * 8192;
                const uint32_t ksubB = (uint32_t)kc * 32768 + (uint32_t)((ks >> 2) & 1) * 16384;
                const int kb = (k7 & 3) * 32;
                #pragma unroll
                for (int mi = 0; mi < 2; ++mi) {
                    uint32_t off = HID_OF + ksubA +
                        sw128((uint32_t)((wm0 + mi * 16 + (lane & 15)) * 128 +
                                         kb + (lane >> 4) * 16));
                    ldsm_x4(ahf[slot][mi], sb + off);
                }
                #pragma unroll
                for (int pi = 0; pi < 2; ++pi) {
                    const int q = lane >> 3;
                    uint32_t off = B2_OF + ksubB + sw128((uint32_t)(
                        (wn0 + pi * 16 + ((q >> 1) << 3) + (lane & 7)) * 128 +
                        kb + (q & 1) * 16));
                    ldsm_x4(bhf[slot][pi], sb + off);
                }
            };
            ld2(0, 0);
            #pragma unroll
            for (int ks = 0; ks < 16; ++ks) {
                const int cur = ks & 1;
                if (ks < 15) ld2(ks + 1, cur ^ 1);
                #pragma unroll
                for (int mi = 0; mi < 2; ++mi)
                    #pragma unroll
                    for (int pi = 0; pi < 2; ++pi)
                        #pragma unroll
                        for (int hh = 0; hh < 2; ++hh)
                            mma_f16(acc[mi][pi * 2 + hh], ahf[cur][mi],
                                    bhf[cur][pi][2 * hh], bhf[cur][pi][2 * hh + 1]);
            }

            // epilogue -> out fp32
            #pragma unroll
            for (int mi = 0; mi < 2; ++mi) {
                #pragma unroll
                for (int ni = 0; ni < 4; ++ni) {
                    int col = wn0 + ni * 8 + (lane & 3) * 2;
                    int rbase = row0 + wm0 + mi * 16 + (lane >> 2);
                    float2 bb = *reinterpret_cast<const float2*>(bias2 + col);
                    #pragma unroll
                    for (int p = 0; p < 2; ++p) {
                        int row = rbase + p * 8;
                        if (row >= N_NODES) continue;
                        *reinterpret_cast<float2*>(out + (size_t)row * D_OUT + col) =
                            make_float2(acc[mi][ni][2 * p] + bb.x,
                                        acc[mi][ni][2 * p + 1] + bb.y);
                    }
                }
            }
        }
        __syncthreads();
        t = tn;
    }
}

// ---------------------------------------------------------------------------
// Launch. Inputs: x, edge_src, edge_dst, edge_val, eps, w1, b1, w2, b2
// ---------------------------------------------------------------------------
extern "C" void kernel_launch(void* const* d_in, const int* in_sizes, int n_in,
                              void* d_out, int out_size)
{
    const float* x        = (const float*)d_in[0];
    const int*   edge_src = (const int*)  d_in[1];
    const int*   edge_dst = (const int*)  d_in[2];
    const float* edge_val = (const float*)d_in[3];
    const float* eps      = (const float*)d_in[4];
    const float* w1       = (const float*)d_in[5];
    const float* b1       = (const float*)d_in[6];
    const float* w2       = (const float*)d_in[7];
    const float* b2       = (const float*)d_in[8];
    float* out = (float*)d_out;

    float* aggp;
    __half *b1h, *b2h;
    cudaGetSymbolAddress((void**)&aggp, g_agg);
    cudaGetSymbolAddress((void**)&b1h,  g_b1h);
    cudaGetSymbolAddress((void**)&b2h,  g_b2h);

    {
        size_t n = (size_t)N_NODES * D_IN / 4;
        init_kernel<<<(int)((n + 255) / 256), 256>>>(x, eps);
    }
    {
        int warps = (N_EDGES + EDGES_PER_WARP - 1) / EDGES_PER_WARP;
        agg_kernel<<<(warps * 32 + 255) / 256, 256>>>(edge_src, edge_dst, edge_val);
    }
    conv_b_kernel<<<(D_HID * D_IN + D_OUT * D_HID + 255) / 256, 256>>>(w1, w2);

    {
        constexpr int SMEM = 180224;   // 176 KB
        cudaFuncSetAttribute(fused_kernel, cudaFuncAttributeMaxDynamicSharedMemorySize, SMEM);
        fused_kernel<<<PGRID, 256, SMEM>>>(aggp, b1h, b2h, b1, b2, out);
    }
}